// round 9
// baseline (speedup 1.0000x reference)
#include <cuda_runtime.h>
#include <cuda_bf16.h>

#define N_PTS   32768
#define S_NBR   32
#define C_IN    64
#define C_OUT   128
#define NS      (N_PTS * S_NBR)   // 1048576
#define EPSBN   1e-5f

// Scratch (device globals; no allocation allowed)
__device__ float  g_ypre[C_OUT * N_PTS];   // [o][n] 16 MB  (feature pre-BN)
__device__ float  g_rpre[C_OUT * N_PTS];   // [o][n] 16 MB  (residual pre-BN)
__device__ float2 g_part[2 * C_OUT * 4];   // partial (sum, sumsq) per (path, o, quarter)

// ---------------------------------------------------------------------------
// Fully fused kernel. Block = 256 threads, 32 points.
// Phase 1 (aggregation): lane = (idx = lane>>3, s4 = lane&7).
//   Warp w owns channels [8w, 8w+8). ptg loop NOT unrolled (register pressure:
//   the 8x unroll pinned 95 regs -> 2 CTAs/SM). Inner ci loop unrolled 8x for
//   MLP. 32-bit offsets into np (fits: 67*1M elements < 2^31).
// Phase 2 (feature GEMV 64->128): warp = 16-output slab as 2x8, lane = point.
// Phase 3 (residual GEMV): same tiling, smem reloaded.
__global__ __launch_bounds__(256) void k_fused(
    const float* __restrict__ xyz,     // [N][3]
    const float* __restrict__ np,      // [67][N][S]
    const float* __restrict__ pf,      // [64][N]
    const float* __restrict__ Wint,    // [64][3]
    const float* __restrict__ bint,    // [64]
    const float* __restrict__ Wfeat,   // [128][64]
    const float* __restrict__ bfeat,   // [128]
    const float* __restrict__ Wres,    // [128][64]
    const float* __restrict__ bres)    // [128]
{
    __shared__ __align__(16) float spos[3 * 32 * 32];  // 12 KB: [k][pt][s]
    __shared__ float  aggs[C_IN][33];                  // padded; reused as pf tile
    __shared__ float4 Ws[C_OUT * (C_IN/4)];            // 32 KB
    __shared__ float  bs[C_OUT];
    __shared__ float4 wq[C_IN];                        // {w0,w1,w2,bias}

    int tid  = threadIdx.x;
    int warp = tid >> 5;
    int lane = tid & 31;
    int n0   = blockIdx.x * 32;

    // ---- stage Wint + Wfeat + relative positions ----
    if (tid < C_IN)
        wq[tid] = make_float4(Wint[tid*3+0], Wint[tid*3+1], Wint[tid*3+2], bint[tid]);
    {
        const float4* W4 = (const float4*)Wfeat;
        #pragma unroll
        for (int i = tid; i < C_OUT * (C_IN/4); i += 256) Ws[i] = W4[i];
        if (tid < C_OUT) bs[tid] = bfeat[tid];
    }
    #pragma unroll
    for (int i = tid; i < 3 * 1024; i += 256) {
        int k  = i >> 10;          // coord 0..2
        int r  = i & 1023;         // pt*32 + s
        int pt = r >> 5;
        spos[i] = np[(unsigned)(k * NS + (n0 << 5) + r)] - xyz[(n0 + pt) * 3 + k];
    }
    __syncthreads();

    // ---- Phase 1: aggregation (ptg NOT unrolled -> low reg pressure) ----
    {
        int s4  = lane & 7;        // 16B chunk within a 128B s-line
        int idx = lane >> 3;       // point within group of 4
        int c0  = warp << 3;       // first channel this warp owns
        const float4* sp4 = (const float4*)spos;

        #pragma unroll 1
        for (int ptg = 0; ptg < 8; ptg++) {
            int pt = (ptg << 2) | idx;
            float4 px = sp4[0 * 256 + (pt << 3) + s4];
            float4 py = sp4[1 * 256 + (pt << 3) + s4];
            float4 pz = sp4[2 * 256 + (pt << 3) + s4];

            // 32-bit element offset: (3+c0)*NS + (n0+pt)*32 + s4*4
            unsigned fo = (unsigned)(3 + c0) * (unsigned)NS
                        + ((unsigned)(n0 + pt) << 5) + ((unsigned)s4 << 2);

            #pragma unroll
            for (int ci = 0; ci < 8; ci++) {
                int c = c0 | ci;
                float4 w = wq[c];                                   // broadcast
                float4 f = *(const float4*)(np + fo + (unsigned)ci * NS);

                float h0 = fmaf(w.x, px.x, fmaf(w.y, py.x, fmaf(w.z, pz.x, w.w)));
                float h1 = fmaf(w.x, px.y, fmaf(w.y, py.y, fmaf(w.z, pz.y, w.w)));
                float h2 = fmaf(w.x, px.z, fmaf(w.y, py.z, fmaf(w.z, pz.z, w.w)));
                float h3 = fmaf(w.x, px.w, fmaf(w.y, py.w, fmaf(w.z, pz.w, w.w)));

                float acc;
                acc = fmaxf(h0, 0.0f) * f.x;
                acc = fmaf(fmaxf(h1, 0.0f), f.y, acc);
                acc = fmaf(fmaxf(h2, 0.0f), f.z, acc);
                acc = fmaf(fmaxf(h3, 0.0f), f.w, acc);

                acc += __shfl_xor_sync(0xffffffffu, acc, 1);
                acc += __shfl_xor_sync(0xffffffffu, acc, 2);
                acc += __shfl_xor_sync(0xffffffffu, acc, 4);
                if (s4 == 0) aggs[c][pt] = acc;
            }
        }
    }
    __syncthreads();

    // ---- Phase 2: feature GEMV (two 8-output half-passes) ----
    {
        int n = n0 + lane;
        #pragma unroll
        for (int half = 0; half < 2; half++) {
            int o0 = warp * 16 + half * 8;
            float acc[8];
            #pragma unroll
            for (int oi = 0; oi < 8; oi++) acc[oi] = bs[o0 + oi];

            #pragma unroll 4
            for (int c4 = 0; c4 < C_IN/4; c4++) {
                float f0 = aggs[c4*4+0][lane];
                float f1 = aggs[c4*4+1][lane];
                float f2 = aggs[c4*4+2][lane];
                float f3 = aggs[c4*4+3][lane];
                #pragma unroll
                for (int oi = 0; oi < 8; oi++) {
                    float4 w4 = Ws[(o0 + oi) * (C_IN/4) + c4];
                    acc[oi] = fmaf(f0, w4.x, acc[oi]);
                    acc[oi] = fmaf(f1, w4.y, acc[oi]);
                    acc[oi] = fmaf(f2, w4.z, acc[oi]);
                    acc[oi] = fmaf(f3, w4.w, acc[oi]);
                }
            }
            #pragma unroll
            for (int oi = 0; oi < 8; oi++)
                g_ypre[(o0 + oi) * N_PTS + n] = acc[oi];   // coalesced
        }
    }
    __syncthreads();   // done reading aggs/Ws before overwrite

    // ---- reload smem with residual operands ----
    {
        const float4* W4 = (const float4*)Wres;
        #pragma unroll
        for (int i = tid; i < C_OUT * (C_IN/4); i += 256) Ws[i] = W4[i];
        if (tid < C_OUT) bs[tid] = bres[tid];
    }
    #pragma unroll
    for (int i = tid; i < C_IN * 32; i += 256) {
        int cc = i >> 5, col = i & 31;
        aggs[cc][col] = pf[cc * N_PTS + n0 + col];   // coalesced
    }
    __syncthreads();

    // ---- Phase 3: residual GEMV (two 8-output half-passes) ----
    {
        int n = n0 + lane;
        #pragma unroll
        for (int half = 0; half < 2; half++) {
            int o0 = warp * 16 + half * 8;
            float acc[8];
            #pragma unroll
            for (int oi = 0; oi < 8; oi++) acc[oi] = bs[o0 + oi];

            #pragma unroll 4
            for (int c4 = 0; c4 < C_IN/4; c4++) {
                float f0 = aggs[c4*4+0][lane];
                float f1 = aggs[c4*4+1][lane];
                float f2 = aggs[c4*4+2][lane];
                float f3 = aggs[c4*4+3][lane];
                #pragma unroll
                for (int oi = 0; oi < 8; oi++) {
                    float4 w4 = Ws[(o0 + oi) * (C_IN/4) + c4];
                    acc[oi] = fmaf(f0, w4.x, acc[oi]);
                    acc[oi] = fmaf(f1, w4.y, acc[oi]);
                    acc[oi] = fmaf(f2, w4.z, acc[oi]);
                    acc[oi] = fmaf(f3, w4.w, acc[oi]);
                }
            }
            #pragma unroll
            for (int oi = 0; oi < 8; oi++)
                g_rpre[(o0 + oi) * N_PTS + n] = acc[oi];
        }
    }
}

// ---------------------------------------------------------------------------
// BN partial stats: 1024 blocks = (path, channel, quarter-row). No atomics.
__global__ __launch_bounds__(256) void k_stats(void)
{
    __shared__ float ws1[8], ws2[8];

    int bid  = blockIdx.x;
    int q    = bid & 3;
    int o    = (bid >> 2) & (C_OUT - 1);
    int path = bid >> 9;
    int tid  = threadIdx.x;

    const float4* src = (const float4*)((path ? g_rpre : g_ypre) + o * N_PTS)
                      + q * (N_PTS / 16);

    float s1 = 0.0f, s2 = 0.0f;
    #pragma unroll
    for (int i = tid; i < N_PTS/16; i += 256) {
        float4 v = src[i];
        s1 += v.x + v.y + v.z + v.w;
        s2 += v.x*v.x + v.y*v.y + v.z*v.z + v.w*v.w;
    }
    #pragma unroll
    for (int off = 16; off; off >>= 1) {
        s1 += __shfl_xor_sync(0xffffffffu, s1, off);
        s2 += __shfl_xor_sync(0xffffffffu, s2, off);
    }
    int warp = tid >> 5, lane = tid & 31;
    if (lane == 0) { ws1[warp] = s1; ws2[warp] = s2; }
    __syncthreads();
    if (tid == 0) {
        float t1 = 0.0f, t2 = 0.0f;
        #pragma unroll
        for (int w = 0; w < 8; w++) { t1 += ws1[w]; t2 += ws2[w]; }
        g_part[bid] = make_float2(t1, t2);
    }
}

// ---------------------------------------------------------------------------
// Finalize: reduce partials + BN coefficients inline, affine + ReLU both
// paths, add, float4 throughout.
__global__ __launch_bounds__(256) void k_final(
    const float* __restrict__ gf, const float* __restrict__ btf,
    const float* __restrict__ gr, const float* __restrict__ btr,
    float* __restrict__ out)
{
    int i4 = blockIdx.x * 256 + threadIdx.x;    // float4 index
    int o  = i4 >> 13;                          // channel (N/4 = 8192 per row)
    const float inv = 1.0f / (float)N_PTS;

    float s1f = 0.0f, s2f = 0.0f, s1r = 0.0f, s2r = 0.0f;
    #pragma unroll
    for (int q = 0; q < 4; q++) {
        float2 pF = g_part[(o << 2) + q];                    // cached/broadcast
        float2 pR = g_part[(1 << 9) + (o << 2) + q];
        s1f += pF.x; s2f += pF.y;
        s1r += pR.x; s2r += pR.y;
    }

    float mf = s1f * inv;
    float vf = s2f * inv - mf * mf;
    float Af = gf[o] * rsqrtf(vf + EPSBN);
    float Bf = btf[o] - mf * Af;

    float mr = s1r * inv;
    float vr = s2r * inv - mr * mr;
    float Ar = gr[o] * rsqrtf(vr + EPSBN);
    float Br = btr[o] - mr * Ar;

    float4 y = ((const float4*)g_ypre)[i4];
    float4 r = ((const float4*)g_rpre)[i4];
    float4 v;
    v.x = fmaxf(fmaf(y.x, Af, Bf), 0.0f) + fmaxf(fmaf(r.x, Ar, Br), 0.0f);
    v.y = fmaxf(fmaf(y.y, Af, Bf), 0.0f) + fmaxf(fmaf(r.y, Ar, Br), 0.0f);
    v.z = fmaxf(fmaf(y.z, Af, Bf), 0.0f) + fmaxf(fmaf(r.z, Ar, Br), 0.0f);
    v.w = fmaxf(fmaf(y.w, Af, Bf), 0.0f) + fmaxf(fmaf(r.w, Ar, Br), 0.0f);
    ((float4*)out)[i4] = v;
}

// ---------------------------------------------------------------------------
extern "C" void kernel_launch(void* const* d_in, const int* in_sizes, int n_in,
                              void* d_out, int out_size) {
    const float* xyz   = (const float*)d_in[0];   // (1, N, 3)
    const float* pf    = (const float*)d_in[1];   // (1, 64, N)
    const float* np    = (const float*)d_in[2];   // (1, 67, N, 32)
    const float* Wint  = (const float*)d_in[3];
    const float* bint  = (const float*)d_in[4];
    const float* Wfeat = (const float*)d_in[5];
    const float* bfeat = (const float*)d_in[6];
    const float* gfeat = (const float*)d_in[7];
    const float* befeat= (const float*)d_in[8];
    const float* Wres  = (const float*)d_in[9];
    const float* bres  = (const float*)d_in[10];
    const float* gres  = (const float*)d_in[11];
    const float* beres = (const float*)d_in[12];
    float* out = (float*)d_out;

    k_fused<<<N_PTS / 32, 256>>>(xyz, np, pf, Wint, bint,
                                 Wfeat, bfeat, Wres, bres);
    k_stats<<<2 * C_OUT * 4, 256>>>();
    k_final<<<(C_OUT * N_PTS / 4) / 256, 256>>>(gfeat, befeat, gres, beres, out);
}

// round 10
// speedup vs baseline: 1.0208x; 1.0208x over previous
#include <cuda_runtime.h>
#include <cuda_bf16.h>

#define N_PTS   32768
#define S_NBR   32
#define C_IN    64
#define C_OUT   128
#define NS      (N_PTS * S_NBR)   // 1048576
#define EPSBN   1e-5f

// Scratch (device globals; no allocation allowed)
__device__ float  g_ypre[C_OUT * N_PTS];   // [o][n] 16 MB  (feature pre-BN)
__device__ float  g_rpre[C_OUT * N_PTS];   // [o][n] 16 MB  (residual pre-BN)
__device__ float2 g_part[2 * C_OUT * 4];   // partial (sum, sumsq) per (path, o, quarter)

// ---------------------------------------------------------------------------
// Fully fused kernel. Block = 256 threads, 32 points.
// Phase 1 (aggregation): lane = (idx = lane>>3, s4 = lane&7).
//   Warp w owns channels [8w, 8w+8). ptg loop unrolled 4x: balances per-warp
//   MLP (32 LDGs in flight) against register pressure (target <=85 regs for
//   3 CTAs/SM). 32-bit offsets into np. Inner ci loop unrolled 8x.
// Phase 2 (feature GEMV 64->128): warp = 16-output slab as 2x8, lane = point.
// Phase 3 (residual GEMV): same tiling, smem reloaded.
__global__ __launch_bounds__(256) void k_fused(
    const float* __restrict__ xyz,     // [N][3]
    const float* __restrict__ np,      // [67][N][S]
    const float* __restrict__ pf,      // [64][N]
    const float* __restrict__ Wint,    // [64][3]
    const float* __restrict__ bint,    // [64]
    const float* __restrict__ Wfeat,   // [128][64]
    const float* __restrict__ bfeat,   // [128]
    const float* __restrict__ Wres,    // [128][64]
    const float* __restrict__ bres)    // [128]
{
    __shared__ __align__(16) float spos[3 * 32 * 32];  // 12 KB: [k][pt][s]
    __shared__ float  aggs[C_IN][33];                  // padded; reused as pf tile
    __shared__ float4 Ws[C_OUT * (C_IN/4)];            // 32 KB
    __shared__ float  bs[C_OUT];
    __shared__ float4 wq[C_IN];                        // {w0,w1,w2,bias}

    int tid  = threadIdx.x;
    int warp = tid >> 5;
    int lane = tid & 31;
    int n0   = blockIdx.x * 32;

    // ---- stage Wint + Wfeat + relative positions ----
    if (tid < C_IN)
        wq[tid] = make_float4(Wint[tid*3+0], Wint[tid*3+1], Wint[tid*3+2], bint[tid]);
    {
        const float4* W4 = (const float4*)Wfeat;
        #pragma unroll
        for (int i = tid; i < C_OUT * (C_IN/4); i += 256) Ws[i] = W4[i];
        if (tid < C_OUT) bs[tid] = bfeat[tid];
    }
    #pragma unroll
    for (int i = tid; i < 3 * 1024; i += 256) {
        int k  = i >> 10;          // coord 0..2
        int r  = i & 1023;         // pt*32 + s
        int pt = r >> 5;
        spos[i] = np[(unsigned)(k * NS + (n0 << 5) + r)] - xyz[(n0 + pt) * 3 + k];
    }
    __syncthreads();

    // ---- Phase 1: aggregation (ptg unrolled 4x: MLP vs regs balance) ----
    {
        int s4  = lane & 7;        // 16B chunk within a 128B s-line
        int idx = lane >> 3;       // point within group of 4
        int c0  = warp << 3;       // first channel this warp owns
        const float4* sp4 = (const float4*)spos;

        #pragma unroll 4
        for (int ptg = 0; ptg < 8; ptg++) {
            int pt = (ptg << 2) | idx;
            float4 px = sp4[0 * 256 + (pt << 3) + s4];
            float4 py = sp4[1 * 256 + (pt << 3) + s4];
            float4 pz = sp4[2 * 256 + (pt << 3) + s4];

            // 32-bit element offset: (3+c0)*NS + (n0+pt)*32 + s4*4
            unsigned fo = (unsigned)(3 + c0) * (unsigned)NS
                        + ((unsigned)(n0 + pt) << 5) + ((unsigned)s4 << 2);

            #pragma unroll
            for (int ci = 0; ci < 8; ci++) {
                int c = c0 | ci;
                float4 w = wq[c];                                   // broadcast
                float4 f = *(const float4*)(np + fo + (unsigned)ci * NS);

                float h0 = fmaf(w.x, px.x, fmaf(w.y, py.x, fmaf(w.z, pz.x, w.w)));
                float h1 = fmaf(w.x, px.y, fmaf(w.y, py.y, fmaf(w.z, pz.y, w.w)));
                float h2 = fmaf(w.x, px.z, fmaf(w.y, py.z, fmaf(w.z, pz.z, w.w)));
                float h3 = fmaf(w.x, px.w, fmaf(w.y, py.w, fmaf(w.z, pz.w, w.w)));

                float acc;
                acc = fmaxf(h0, 0.0f) * f.x;
                acc = fmaf(fmaxf(h1, 0.0f), f.y, acc);
                acc = fmaf(fmaxf(h2, 0.0f), f.z, acc);
                acc = fmaf(fmaxf(h3, 0.0f), f.w, acc);

                acc += __shfl_xor_sync(0xffffffffu, acc, 1);
                acc += __shfl_xor_sync(0xffffffffu, acc, 2);
                acc += __shfl_xor_sync(0xffffffffu, acc, 4);
                if (s4 == 0) aggs[c][pt] = acc;
            }
        }
    }
    __syncthreads();

    // ---- Phase 2: feature GEMV (two 8-output half-passes) ----
    {
        int n = n0 + lane;
        #pragma unroll
        for (int half = 0; half < 2; half++) {
            int o0 = warp * 16 + half * 8;
            float acc[8];
            #pragma unroll
            for (int oi = 0; oi < 8; oi++) acc[oi] = bs[o0 + oi];

            #pragma unroll 4
            for (int c4 = 0; c4 < C_IN/4; c4++) {
                float f0 = aggs[c4*4+0][lane];
                float f1 = aggs[c4*4+1][lane];
                float f2 = aggs[c4*4+2][lane];
                float f3 = aggs[c4*4+3][lane];
                #pragma unroll
                for (int oi = 0; oi < 8; oi++) {
                    float4 w4 = Ws[(o0 + oi) * (C_IN/4) + c4];
                    acc[oi] = fmaf(f0, w4.x, acc[oi]);
                    acc[oi] = fmaf(f1, w4.y, acc[oi]);
                    acc[oi] = fmaf(f2, w4.z, acc[oi]);
                    acc[oi] = fmaf(f3, w4.w, acc[oi]);
                }
            }
            #pragma unroll
            for (int oi = 0; oi < 8; oi++)
                g_ypre[(o0 + oi) * N_PTS + n] = acc[oi];   // coalesced
        }
    }
    __syncthreads();   // done reading aggs/Ws before overwrite

    // ---- reload smem with residual operands ----
    {
        const float4* W4 = (const float4*)Wres;
        #pragma unroll
        for (int i = tid; i < C_OUT * (C_IN/4); i += 256) Ws[i] = W4[i];
        if (tid < C_OUT) bs[tid] = bres[tid];
    }
    #pragma unroll
    for (int i = tid; i < C_IN * 32; i += 256) {
        int cc = i >> 5, col = i & 31;
        aggs[cc][col] = pf[cc * N_PTS + n0 + col];   // coalesced
    }
    __syncthreads();

    // ---- Phase 3: residual GEMV (two 8-output half-passes) ----
    {
        int n = n0 + lane;
        #pragma unroll
        for (int half = 0; half < 2; half++) {
            int o0 = warp * 16 + half * 8;
            float acc[8];
            #pragma unroll
            for (int oi = 0; oi < 8; oi++) acc[oi] = bs[o0 + oi];

            #pragma unroll 4
            for (int c4 = 0; c4 < C_IN/4; c4++) {
                float f0 = aggs[c4*4+0][lane];
                float f1 = aggs[c4*4+1][lane];
                float f2 = aggs[c4*4+2][lane];
                float f3 = aggs[c4*4+3][lane];
                #pragma unroll
                for (int oi = 0; oi < 8; oi++) {
                    float4 w4 = Ws[(o0 + oi) * (C_IN/4) + c4];
                    acc[oi] = fmaf(f0, w4.x, acc[oi]);
                    acc[oi] = fmaf(f1, w4.y, acc[oi]);
                    acc[oi] = fmaf(f2, w4.z, acc[oi]);
                    acc[oi] = fmaf(f3, w4.w, acc[oi]);
                }
            }
            #pragma unroll
            for (int oi = 0; oi < 8; oi++)
                g_rpre[(o0 + oi) * N_PTS + n] = acc[oi];
        }
    }
}

// ---------------------------------------------------------------------------
// BN partial stats: 1024 blocks = (path, channel, quarter-row). No atomics.
__global__ __launch_bounds__(256) void k_stats(void)
{
    __shared__ float ws1[8], ws2[8];

    int bid  = blockIdx.x;
    int q    = bid & 3;
    int o    = (bid >> 2) & (C_OUT - 1);
    int path = bid >> 9;
    int tid  = threadIdx.x;

    const float4* src = (const float4*)((path ? g_rpre : g_ypre) + o * N_PTS)
                      + q * (N_PTS / 16);

    float s1 = 0.0f, s2 = 0.0f;
    #pragma unroll
    for (int i = tid; i < N_PTS/16; i += 256) {
        float4 v = src[i];
        s1 += v.x + v.y + v.z + v.w;
        s2 += v.x*v.x + v.y*v.y + v.z*v.z + v.w*v.w;
    }
    #pragma unroll
    for (int off = 16; off; off >>= 1) {
        s1 += __shfl_xor_sync(0xffffffffu, s1, off);
        s2 += __shfl_xor_sync(0xffffffffu, s2, off);
    }
    int warp = tid >> 5, lane = tid & 31;
    if (lane == 0) { ws1[warp] = s1; ws2[warp] = s2; }
    __syncthreads();
    if (tid == 0) {
        float t1 = 0.0f, t2 = 0.0f;
        #pragma unroll
        for (int w = 0; w < 8; w++) { t1 += ws1[w]; t2 += ws2[w]; }
        g_part[bid] = make_float2(t1, t2);
    }
}

// ---------------------------------------------------------------------------
// Finalize: reduce partials + BN coefficients inline, affine + ReLU both
// paths, add, float4 throughout.
__global__ __launch_bounds__(256) void k_final(
    const float* __restrict__ gf, const float* __restrict__ btf,
    const float* __restrict__ gr, const float* __restrict__ btr,
    float* __restrict__ out)
{
    int i4 = blockIdx.x * 256 + threadIdx.x;    // float4 index
    int o  = i4 >> 13;                          // channel (N/4 = 8192 per row)
    const float inv = 1.0f / (float)N_PTS;

    float s1f = 0.0f, s2f = 0.0f, s1r = 0.0f, s2r = 0.0f;
    #pragma unroll
    for (int q = 0; q < 4; q++) {
        float2 pF = g_part[(o << 2) + q];                    // cached/broadcast
        float2 pR = g_part[(1 << 9) + (o << 2) + q];
        s1f += pF.x; s2f += pF.y;
        s1r += pR.x; s2r += pR.y;
    }

    float mf = s1f * inv;
    float vf = s2f * inv - mf * mf;
    float Af = gf[o] * rsqrtf(vf + EPSBN);
    float Bf = btf[o] - mf * Af;

    float mr = s1r * inv;
    float vr = s2r * inv - mr * mr;
    float Ar = gr[o] * rsqrtf(vr + EPSBN);
    float Br = btr[o] - mr * Ar;

    float4 y = ((const float4*)g_ypre)[i4];
    float4 r = ((const float4*)g_rpre)[i4];
    float4 v;
    v.x = fmaxf(fmaf(y.x, Af, Bf), 0.0f) + fmaxf(fmaf(r.x, Ar, Br), 0.0f);
    v.y = fmaxf(fmaf(y.y, Af, Bf), 0.0f) + fmaxf(fmaf(r.y, Ar, Br), 0.0f);
    v.z = fmaxf(fmaf(y.z, Af, Bf), 0.0f) + fmaxf(fmaf(r.z, Ar, Br), 0.0f);
    v.w = fmaxf(fmaf(y.w, Af, Bf), 0.0f) + fmaxf(fmaf(r.w, Ar, Br), 0.0f);
    ((float4*)out)[i4] = v;
}

// ---------------------------------------------------------------------------
extern "C" void kernel_launch(void* const* d_in, const int* in_sizes, int n_in,
                              void* d_out, int out_size) {
    const float* xyz   = (const float*)d_in[0];   // (1, N, 3)
    const float* pf    = (const float*)d_in[1];   // (1, 64, N)
    const float* np    = (const float*)d_in[2];   // (1, 67, N, 32)
    const float* Wint  = (const float*)d_in[3];
    const float* bint  = (const float*)d_in[4];
    const float* Wfeat = (const float*)d_in[5];
    const float* bfeat = (const float*)d_in[6];
    const float* gfeat = (const float*)d_in[7];
    const float* befeat= (const float*)d_in[8];
    const float* Wres  = (const float*)d_in[9];
    const float* bres  = (const float*)d_in[10];
    const float* gres  = (const float*)d_in[11];
    const float* beres = (const float*)d_in[12];
    float* out = (float*)d_out;

    k_fused<<<N_PTS / 32, 256>>>(xyz, np, pf, Wint, bint,
                                 Wfeat, bfeat, Wres, bres);
    k_stats<<<2 * C_OUT * 4, 256>>>();
    k_final<<<(C_OUT * N_PTS / 4) / 256, 256>>>(gfeat, befeat, gres, beres, out);
}

// round 11
// speedup vs baseline: 1.0229x; 1.0021x over previous
#include <cuda_runtime.h>
#include <cstdint>

#define N_PTS   32768
#define S_NBR   32
#define C_IN    64
#define C_OUT   128
#define NS      (N_PTS * S_NBR)   // 1048576
#define EPSBN   1e-5f

// Scratch (device globals; no allocation allowed)
__device__ float  g_ypre[C_OUT * N_PTS];   // [o][n] 16 MB
__device__ float  g_rpre[C_OUT * N_PTS];   // [o][n] 16 MB
__device__ float2 g_part[2 * C_OUT * 4];   // partial (sum,sumsq) per (path,o,quarter)

// ---- dynamic smem layout (floats unless noted) ----
// tile:  2 bufs x 8 ch x 32 pt x 32 s   = 16384 floats (65536 B)  [reused by GEMV]
// spos:  3*32*32                        =  3072 floats (12288 B)
// aggs:  64*33 (padded)                 =  2112 floats ( 8448 B)
// wq:    64 float4                      =   256 floats ( 1024 B)
// mbar:  2 x u64                        (16 B)
#define SPOS_OFF   16384
#define AGGS_OFF   (SPOS_OFF + 3072)          // 19456
#define WQ_OFF     (AGGS_OFF + 2112)          // 21568
#define MBAR_BYTE  ((WQ_OFF + 256) * 4)       // 87296 (16B aligned)
#define SMEM_BYTES (MBAR_BYTE + 32)           // 87328

// GEMV staging inside the tile region (floats):
#define WS_OFF     0                          // 128*16 float4 = 2048 float4 = 8192 floats
#define BS_OFF     8192                       // 128 floats
#define PF_OFF     8320                       // 64*32 = 2048 floats

// ---------------------------------------------------------------------------
__device__ __forceinline__ uint32_t smem_u32(const void* p) {
    uint32_t a;
    asm("{ .reg .u64 t; cvta.to.shared.u64 t, %1; cvt.u32.u64 %0, t; }"
        : "=r"(a) : "l"(p));
    return a;
}
__device__ __forceinline__ void bulk_g2s(uint32_t dst, const void* src,
                                         uint32_t bytes, uint32_t mbar) {
    asm volatile(
        "cp.async.bulk.shared::cta.global.mbarrier::complete_tx::bytes "
        "[%0], [%1], %2, [%3];"
        :: "r"(dst), "l"(src), "r"(bytes), "r"(mbar) : "memory");
}
__device__ __forceinline__ void mbar_init(uint32_t mbar, uint32_t cnt) {
    asm volatile("mbarrier.init.shared.b64 [%0], %1;" :: "r"(mbar), "r"(cnt) : "memory");
}
__device__ __forceinline__ void mbar_expect_tx(uint32_t mbar, uint32_t bytes) {
    asm volatile("mbarrier.arrive.expect_tx.shared.b64 _, [%0], %1;"
                 :: "r"(mbar), "r"(bytes) : "memory");
}
__device__ __forceinline__ void mbar_wait(uint32_t mbar, uint32_t parity) {
    asm volatile(
        "{\n\t.reg .pred P;\n\t"
        "W_%=:\n\t"
        "mbarrier.try_wait.parity.acquire.cta.shared::cta.b64 P, [%0], %1, 0x989680;\n\t"
        "@!P bra W_%=;\n\t}"
        :: "r"(mbar), "r"(parity) : "memory");
}

// ---------------------------------------------------------------------------
// Fused kernel. Block = 256 threads, 32 points, dynamic smem.
// Phase 1: 8 chunks of 8 channels. Features arrive via double-buffered
//   cp.async.bulk (8 x 4KB contiguous copies per chunk, mbarrier-tracked).
//   Warp = 1 channel/chunk; lane = (idx = lane>>3, s4 = lane&7); per-warp
//   feature reads are conflict-free LDS.128. 3-shfl reduce over s4 group.
// Phase 2/3: GEMV 64->128 (warp = 16-output slab as 2x8, lane = point);
//   weights/bias/pf staged into the (now free) tile region.
__global__ __launch_bounds__(256) void k_fused(
    const float* __restrict__ xyz,     // [N][3]
    const float* __restrict__ np,      // [67][N][S]
    const float* __restrict__ pf,      // [64][N]
    const float* __restrict__ Wint,    // [64][3]
    const float* __restrict__ bint,    // [64]
    const float* __restrict__ Wfeat,   // [128][64]
    const float* __restrict__ bfeat,   // [128]
    const float* __restrict__ Wres,    // [128][64]
    const float* __restrict__ bres)    // [128]
{
    extern __shared__ __align__(16) float smf[];
    float*  tile = smf;                 // 16384 floats
    float*  spos = smf + SPOS_OFF;      // [k][pt][s]
    float*  aggs = smf + AGGS_OFF;      // [c][33]
    float4* wq   = (float4*)(smf + WQ_OFF);
    uint32_t smem_base = smem_u32(smf);
    uint32_t mbar0 = smem_base + MBAR_BYTE;

    int tid  = threadIdx.x;
    int warp = tid >> 5;
    int lane = tid & 31;
    int n0   = blockIdx.x * 32;

    // ---- init barriers, kick off first two chunks ----
    if (tid == 0) {
        mbar_init(mbar0, 1);
        mbar_init(mbar0 + 8, 1);
        asm volatile("fence.proxy.async.shared::cta;" ::: "memory");
    }
    __syncthreads();
    if (tid == 0) {
        #pragma unroll
        for (int k = 0; k < 2; k++) {
            uint32_t mb = mbar0 + k * 8;
            mbar_expect_tx(mb, 32768u);
            const float* src = np + (size_t)(3 + k * 8) * NS + ((size_t)n0 << 5);
            #pragma unroll
            for (int cc = 0; cc < 8; cc++)
                bulk_g2s(smem_base + (uint32_t)(k * 8 + cc) * 4096u,
                         src + (size_t)cc * NS, 4096u, mb);
        }
    }

    // ---- stage wq + relative positions (overlaps the bulk copies) ----
    if (tid < C_IN)
        wq[tid] = make_float4(Wint[tid*3+0], Wint[tid*3+1], Wint[tid*3+2], bint[tid]);
    #pragma unroll
    for (int i = tid; i < 3 * 1024; i += 256) {
        int k  = i >> 10;
        int r  = i & 1023;
        int pt = r >> 5;
        spos[i] = np[(unsigned)(k * NS + (n0 << 5) + r)] - xyz[(n0 + pt) * 3 + k];
    }
    __syncthreads();

    // ---- Phase 1: 8 chunks of 8 channels ----
    {
        int s4  = lane & 7;
        int idx = lane >> 3;
        const float4* sp4 = (const float4*)spos;

        #pragma unroll 1
        for (int k = 0; k < 8; k++) {
            int b  = k & 1;
            int ph = (k >> 1) & 1;
            mbar_wait(mbar0 + b * 8, (uint32_t)ph);

            int c = k * 8 + warp;           // this warp's channel this chunk
            float4 w = wq[c];
            const float4* ft = (const float4*)(tile + (b * 8 + warp) * 1024);

            #pragma unroll
            for (int ptg = 0; ptg < 8; ptg++) {
                int pt = (ptg << 2) | idx;
                float4 f  = ft[(pt << 3) + s4];            // LDS.128, 512B/warp
                float4 px = sp4[0 * 256 + (pt << 3) + s4];
                float4 py = sp4[1 * 256 + (pt << 3) + s4];
                float4 pz = sp4[2 * 256 + (pt << 3) + s4];

                float h0 = fmaf(w.x, px.x, fmaf(w.y, py.x, fmaf(w.z, pz.x, w.w)));
                float h1 = fmaf(w.x, px.y, fmaf(w.y, py.y, fmaf(w.z, pz.y, w.w)));
                float h2 = fmaf(w.x, px.z, fmaf(w.y, py.z, fmaf(w.z, pz.z, w.w)));
                float h3 = fmaf(w.x, px.w, fmaf(w.y, py.w, fmaf(w.z, pz.w, w.w)));

                float acc;
                acc = fmaxf(h0, 0.0f) * f.x;
                acc = fmaf(fmaxf(h1, 0.0f), f.y, acc);
                acc = fmaf(fmaxf(h2, 0.0f), f.z, acc);
                acc = fmaf(fmaxf(h3, 0.0f), f.w, acc);

                acc += __shfl_xor_sync(0xffffffffu, acc, 1);
                acc += __shfl_xor_sync(0xffffffffu, acc, 2);
                acc += __shfl_xor_sync(0xffffffffu, acc, 4);
                if (s4 == 0) aggs[c * 33 + pt] = acc;
            }
            __syncthreads();                 // all warps done with buffer b

            if (tid == 0 && k < 6) {         // refill buffer b with chunk k+2
                int kn = k + 2;
                uint32_t mb = mbar0 + b * 8;
                mbar_expect_tx(mb, 32768u);
                const float* src = np + (size_t)(3 + kn * 8) * NS + ((size_t)n0 << 5);
                #pragma unroll
                for (int cc = 0; cc < 8; cc++)
                    bulk_g2s(smem_base + (uint32_t)(b * 8 + cc) * 4096u,
                             src + (size_t)cc * NS, 4096u, mb);
            }
        }
    }

    // ---- stage feature-path GEMV operands into the free tile region ----
    {
        const float4* W4 = (const float4*)Wfeat;
        float4* Ws = (float4*)(tile + WS_OFF);
        #pragma unroll
        for (int i = tid; i < C_OUT * (C_IN/4); i += 256) Ws[i] = W4[i];
        if (tid < C_OUT) tile[BS_OFF + tid] = bfeat[tid];
    }
    __syncthreads();

    // ---- Phase 2: feature GEMV (two 8-output half-passes) ----
    {
        const float4* Ws = (const float4*)(tile + WS_OFF);
        int n = n0 + lane;
        #pragma unroll
        for (int half = 0; half < 2; half++) {
            int o0 = warp * 16 + half * 8;
            float acc[8];
            #pragma unroll
            for (int oi = 0; oi < 8; oi++) acc[oi] = tile[BS_OFF + o0 + oi];

            #pragma unroll 4
            for (int c4 = 0; c4 < C_IN/4; c4++) {
                float f0 = aggs[(c4*4+0) * 33 + lane];
                float f1 = aggs[(c4*4+1) * 33 + lane];
                float f2 = aggs[(c4*4+2) * 33 + lane];
                float f3 = aggs[(c4*4+3) * 33 + lane];
                #pragma unroll
                for (int oi = 0; oi < 8; oi++) {
                    float4 w4 = Ws[(o0 + oi) * (C_IN/4) + c4];
                    acc[oi] = fmaf(f0, w4.x, acc[oi]);
                    acc[oi] = fmaf(f1, w4.y, acc[oi]);
                    acc[oi] = fmaf(f2, w4.z, acc[oi]);
                    acc[oi] = fmaf(f3, w4.w, acc[oi]);
                }
            }
            #pragma unroll
            for (int oi = 0; oi < 8; oi++)
                g_ypre[(o0 + oi) * N_PTS + n] = acc[oi];   // coalesced
        }
    }
    __syncthreads();

    // ---- stage residual operands ----
    {
        const float4* W4 = (const float4*)Wres;
        float4* Ws = (float4*)(tile + WS_OFF);
        #pragma unroll
        for (int i = tid; i < C_OUT * (C_IN/4); i += 256) Ws[i] = W4[i];
        if (tid < C_OUT) tile[BS_OFF + tid] = bres[tid];
    }
    #pragma unroll
    for (int i = tid; i < C_IN * 32; i += 256) {
        int cc = i >> 5, col = i & 31;
        tile[PF_OFF + i] = pf[cc * N_PTS + n0 + col];   // coalesced
    }
    __syncthreads();

    // ---- Phase 3: residual GEMV ----
    {
        const float4* Ws = (const float4*)(tile + WS_OFF);
        int n = n0 + lane;
        #pragma unroll
        for (int half = 0; half < 2; half++) {
            int o0 = warp * 16 + half * 8;
            float acc[8];
            #pragma unroll
            for (int oi = 0; oi < 8; oi++) acc[oi] = tile[BS_OFF + o0 + oi];

            #pragma unroll 4
            for (int c4 = 0; c4 < C_IN/4; c4++) {
                float f0 = tile[PF_OFF + (c4*4+0) * 32 + lane];
                float f1 = tile[PF_OFF + (c4*4+1) * 32 + lane];
                float f2 = tile[PF_OFF + (c4*4+2) * 32 + lane];
                float f3 = tile[PF_OFF + (c4*4+3) * 32 + lane];
                #pragma unroll
                for (int oi = 0; oi < 8; oi++) {
                    float4 w4 = Ws[(o0 + oi) * (C_IN/4) + c4];
                    acc[oi] = fmaf(f0, w4.x, acc[oi]);
                    acc[oi] = fmaf(f1, w4.y, acc[oi]);
                    acc[oi] = fmaf(f2, w4.z, acc[oi]);
                    acc[oi] = fmaf(f3, w4.w, acc[oi]);
                }
            }
            #pragma unroll
            for (int oi = 0; oi < 8; oi++)
                g_rpre[(o0 + oi) * N_PTS + n] = acc[oi];
        }
    }
}

// ---------------------------------------------------------------------------
// BN partial stats: 1024 blocks = (path, channel, quarter-row). No atomics.
__global__ __launch_bounds__(256) void k_stats(void)
{
    __shared__ float ws1[8], ws2[8];

    int bid  = blockIdx.x;
    int q    = bid & 3;
    int o    = (bid >> 2) & (C_OUT - 1);
    int path = bid >> 9;
    int tid  = threadIdx.x;

    const float4* src = (const float4*)((path ? g_rpre : g_ypre) + o * N_PTS)
                      + q * (N_PTS / 16);

    float s1 = 0.0f, s2 = 0.0f;
    #pragma unroll
    for (int i = tid; i < N_PTS/16; i += 256) {
        float4 v = src[i];
        s1 += v.x + v.y + v.z + v.w;
        s2 += v.x*v.x + v.y*v.y + v.z*v.z + v.w*v.w;
    }
    #pragma unroll
    for (int off = 16; off; off >>= 1) {
        s1 += __shfl_xor_sync(0xffffffffu, s1, off);
        s2 += __shfl_xor_sync(0xffffffffu, s2, off);
    }
    int warp = tid >> 5, lane = tid & 31;
    if (lane == 0) { ws1[warp] = s1; ws2[warp] = s2; }
    __syncthreads();
    if (tid == 0) {
        float t1 = 0.0f, t2 = 0.0f;
        #pragma unroll
        for (int w = 0; w < 8; w++) { t1 += ws1[w]; t2 += ws2[w]; }
        g_part[bid] = make_float2(t1, t2);
    }
}

// ---------------------------------------------------------------------------
// Finalize: reduce partials + BN coefficients inline, affine + ReLU both
// paths, add, float4 throughout.
__global__ __launch_bounds__(256) void k_final(
    const float* __restrict__ gf, const float* __restrict__ btf,
    const float* __restrict__ gr, const float* __restrict__ btr,
    float* __restrict__ out)
{
    int i4 = blockIdx.x * 256 + threadIdx.x;    // float4 index
    int o  = i4 >> 13;                          // channel
    const float inv = 1.0f / (float)N_PTS;

    float s1f = 0.0f, s2f = 0.0f, s1r = 0.0f, s2r = 0.0f;
    #pragma unroll
    for (int q = 0; q < 4; q++) {
        float2 pF = g_part[(o << 2) + q];
        float2 pR = g_part[(1 << 9) + (o << 2) + q];
        s1f += pF.x; s2f += pF.y;
        s1r += pR.x; s2r += pR.y;
    }

    float mf = s1f * inv;
    float vf = s2f * inv - mf * mf;
    float Af = gf[o] * rsqrtf(vf + EPSBN);
    float Bf = btf[o] - mf * Af;

    float mr = s1r * inv;
    float vr = s2r * inv - mr * mr;
    float Ar = gr[o] * rsqrtf(vr + EPSBN);
    float Br = btr[o] - mr * Ar;

    float4 y = ((const float4*)g_ypre)[i4];
    float4 r = ((const float4*)g_rpre)[i4];
    float4 v;
    v.x = fmaxf(fmaf(y.x, Af, Bf), 0.0f) + fmaxf(fmaf(r.x, Ar, Br), 0.0f);
    v.y = fmaxf(fmaf(y.y, Af, Bf), 0.0f) + fmaxf(fmaf(r.y, Ar, Br), 0.0f);
    v.z = fmaxf(fmaf(y.z, Af, Bf), 0.0f) + fmaxf(fmaf(r.z, Ar, Br), 0.0f);
    v.w = fmaxf(fmaf(y.w, Af, Bf), 0.0f) + fmaxf(fmaf(r.w, Ar, Br), 0.0f);
    ((float4*)out)[i4] = v;
}

// ---------------------------------------------------------------------------
extern "C" void kernel_launch(void* const* d_in, const int* in_sizes, int n_in,
                              void* d_out, int out_size) {
    const float* xyz   = (const float*)d_in[0];
    const float* pf    = (const float*)d_in[1];
    const float* np    = (const float*)d_in[2];
    const float* Wint  = (const float*)d_in[3];
    const float* bint  = (const float*)d_in[4];
    const float* Wfeat = (const float*)d_in[5];
    const float* bfeat = (const float*)d_in[6];
    const float* gfeat = (const float*)d_in[7];
    const float* befeat= (const float*)d_in[8];
    const float* Wres  = (const float*)d_in[9];
    const float* bres  = (const float*)d_in[10];
    const float* gres  = (const float*)d_in[11];
    const float* beres = (const float*)d_in[12];
    float* out = (float*)d_out;

    static bool attr_done = false;
    if (!attr_done) {
        cudaFuncSetAttribute(k_fused, cudaFuncAttributeMaxDynamicSharedMemorySize,
                             SMEM_BYTES);
        attr_done = true;
    }

    k_fused<<<N_PTS / 32, 256, SMEM_BYTES>>>(xyz, np, pf, Wint, bint,
                                             Wfeat, bfeat, Wres, bres);
    k_stats<<<2 * C_OUT * 4, 256>>>();
    k_final<<<(C_OUT * N_PTS / 4) / 256, 256>>>(gfeat, befeat, gres, beres, out);
}

// round 12
// speedup vs baseline: 1.1276x; 1.1023x over previous
#include <cuda_runtime.h>
#include <cstdint>

#define N_PTS   32768
#define S_NBR   32
#define C_IN    64
#define C_OUT   128
#define NS      (N_PTS * S_NBR)   // 1048576
#define EPSBN   1e-5f

// Scratch (device globals; no allocation allowed)
__device__ float  g_ypre[C_OUT * N_PTS];   // [o][n] 16 MB
__device__ float  g_rpre[C_OUT * N_PTS];   // [o][n] 16 MB
__device__ float2 g_part[2 * C_OUT * 4];   // partial (sum,sumsq) per (path,o,quarter)

// ---- dynamic smem layout (float offsets) ----
// tile:  2 bufs x 8 ch x 32 pt x 32 s = 16384 floats (65536 B) [reused by GEMV]
// aggs:  64*32                        =  2048 floats ( 8192 B)
// wq:    64 float4                    =   256 floats ( 1024 B)
// mbar:  2 x u64
#define AGGS_OFF   16384
#define WQ_OFF     (AGGS_OFF + 2048)          // 18432
#define MBAR_BYTE  ((WQ_OFF + 256) * 4)       // 74752
#define SMEM_BYTES (MBAR_BYTE + 32)           // 74784

// GEMV staging inside the tile region (float offsets):
#define WS_OFF     0                          // 2048 float4 = 8192 floats
#define BS_OFF     8192                       // 128 floats
#define PF_OFF     8320                       // 2048 floats

// ---------------------------------------------------------------------------
__device__ __forceinline__ uint32_t smem_u32(const void* p) {
    uint32_t a;
    asm("{ .reg .u64 t; cvta.to.shared.u64 t, %1; cvt.u32.u64 %0, t; }"
        : "=r"(a) : "l"(p));
    return a;
}
__device__ __forceinline__ void bulk_g2s(uint32_t dst, const void* src,
                                         uint32_t bytes, uint32_t mbar) {
    asm volatile(
        "cp.async.bulk.shared::cta.global.mbarrier::complete_tx::bytes "
        "[%0], [%1], %2, [%3];"
        :: "r"(dst), "l"(src), "r"(bytes), "r"(mbar) : "memory");
}
__device__ __forceinline__ void mbar_init(uint32_t mbar, uint32_t cnt) {
    asm volatile("mbarrier.init.shared.b64 [%0], %1;" :: "r"(mbar), "r"(cnt) : "memory");
}
__device__ __forceinline__ void mbar_expect_tx(uint32_t mbar, uint32_t bytes) {
    asm volatile("mbarrier.arrive.expect_tx.shared.b64 _, [%0], %1;"
                 :: "r"(mbar), "r"(bytes) : "memory");
}
__device__ __forceinline__ void mbar_wait(uint32_t mbar, uint32_t parity) {
    asm volatile(
        "{\n\t.reg .pred P;\n\t"
        "W_%=:\n\t"
        "mbarrier.try_wait.parity.acquire.cta.shared::cta.b64 P, [%0], %1, 0x989680;\n\t"
        "@!P bra W_%=;\n\t}"
        :: "r"(mbar), "r"(parity) : "memory");
}

// ---------------------------------------------------------------------------
// Fused kernel. Block = 256 threads, 32 points, dynamic smem (~73 KB -> 3 CTAs/SM).
// Phase 1: 8 chunks of 8 channels via double-buffered cp.async.bulk.
//   Warp owns 4 FIXED points (pt = 4*warp + (lane>>3)); s4 = lane&7.
//   Positions live in 12 registers for the whole phase (loaded once from
//   global, coalesced). Inner loop = 1 LDS.128 (feature) + 1 broadcast (wq)
//   per channel -> 4x less L1 traffic than R11. 3-shfl reduce over s4 group.
// Phase 2/3: GEMV 64->128 (warp = 16-output slab as 2x8, lane = point);
//   weights/bias/pf staged into the freed tile region.
__global__ __launch_bounds__(256) void k_fused(
    const float* __restrict__ xyz,     // [N][3]
    const float* __restrict__ np,      // [67][N][S]
    const float* __restrict__ pf,      // [64][N]
    const float* __restrict__ Wint,    // [64][3]
    const float* __restrict__ bint,    // [64]
    const float* __restrict__ Wfeat,   // [128][64]
    const float* __restrict__ bfeat,   // [128]
    const float* __restrict__ Wres,    // [128][64]
    const float* __restrict__ bres)    // [128]
{
    extern __shared__ __align__(16) float smf[];
    float*  tile = smf;                 // 16384 floats
    float*  aggs = smf + AGGS_OFF;      // [c][32]
    float4* wq   = (float4*)(smf + WQ_OFF);
    uint32_t smem_base = smem_u32(smf);
    uint32_t mbar0 = smem_base + MBAR_BYTE;

    int tid  = threadIdx.x;
    int warp = tid >> 5;
    int lane = tid & 31;
    int n0   = blockIdx.x * 32;

    // ---- init barriers, kick off first two chunks ----
    if (tid == 0) {
        mbar_init(mbar0, 1);
        mbar_init(mbar0 + 8, 1);
        asm volatile("fence.proxy.async.shared::cta;" ::: "memory");
    }
    __syncthreads();
    if (tid == 0) {
        #pragma unroll
        for (int k = 0; k < 2; k++) {
            uint32_t mb = mbar0 + k * 8;
            mbar_expect_tx(mb, 32768u);
            const float* src = np + (size_t)(3 + k * 8) * NS + ((size_t)n0 << 5);
            #pragma unroll
            for (int cc = 0; cc < 8; cc++)
                bulk_g2s(smem_base + (uint32_t)(k * 8 + cc) * 4096u,
                         src + (size_t)cc * NS, 4096u, mb);
        }
    }

    // ---- stage wq (overlaps bulk copies) ----
    if (tid < C_IN)
        wq[tid] = make_float4(Wint[tid*3+0], Wint[tid*3+1], Wint[tid*3+2], bint[tid]);

    // ---- positions: loaded once into registers ----
    int s4  = lane & 7;
    int idx = lane >> 3;
    int pt  = (warp << 2) | idx;        // this thread's point (fixed)
    int n   = n0 + pt;
    float4 px, py, pz;
    {
        unsigned po = ((unsigned)n << 5) + ((unsigned)s4 << 2);
        px = *(const float4*)(np + 0u * NS + po);
        py = *(const float4*)(np + 1u * NS + po);
        pz = *(const float4*)(np + 2u * NS + po);
        float x0 = xyz[n*3+0], x1 = xyz[n*3+1], x2 = xyz[n*3+2];
        px.x -= x0; px.y -= x0; px.z -= x0; px.w -= x0;
        py.x -= x1; py.y -= x1; py.z -= x1; py.w -= x1;
        pz.x -= x2; pz.y -= x2; pz.z -= x2; pz.w -= x2;
    }
    __syncthreads();   // wq visible

    // ---- Phase 1: 8 chunks of 8 channels ----
    {
        const float4* tile4 = (const float4*)tile;
        #pragma unroll 1
        for (int k = 0; k < 8; k++) {
            int b  = k & 1;
            int ph = (k >> 1) & 1;
            mbar_wait(mbar0 + b * 8, (uint32_t)ph);

            #pragma unroll
            for (int ci = 0; ci < 8; ci++) {
                int c = k * 8 + ci;
                float4 w = wq[c];                                   // broadcast
                float4 f = tile4[(b * 8 + ci) * 256 + (pt << 3) + s4]; // 512B/warp

                float h0 = fmaf(w.x, px.x, fmaf(w.y, py.x, fmaf(w.z, pz.x, w.w)));
                float h1 = fmaf(w.x, px.y, fmaf(w.y, py.y, fmaf(w.z, pz.y, w.w)));
                float h2 = fmaf(w.x, px.z, fmaf(w.y, py.z, fmaf(w.z, pz.z, w.w)));
                float h3 = fmaf(w.x, px.w, fmaf(w.y, py.w, fmaf(w.z, pz.w, w.w)));

                float acc;
                acc = fmaxf(h0, 0.0f) * f.x;
                acc = fmaf(fmaxf(h1, 0.0f), f.y, acc);
                acc = fmaf(fmaxf(h2, 0.0f), f.z, acc);
                acc = fmaf(fmaxf(h3, 0.0f), f.w, acc);

                acc += __shfl_xor_sync(0xffffffffu, acc, 1);
                acc += __shfl_xor_sync(0xffffffffu, acc, 2);
                acc += __shfl_xor_sync(0xffffffffu, acc, 4);
                if (s4 == 0) aggs[c * 32 + pt] = acc;   // 4 lanes, conflict-free
            }
            __syncthreads();                 // all warps done with buffer b

            if (tid == 0 && k < 6) {         // refill buffer b with chunk k+2
                int kn = k + 2;
                uint32_t mb = mbar0 + b * 8;
                mbar_expect_tx(mb, 32768u);
                const float* src = np + (size_t)(3 + kn * 8) * NS + ((size_t)n0 << 5);
                #pragma unroll
                for (int cc = 0; cc < 8; cc++)
                    bulk_g2s(smem_base + (uint32_t)(b * 8 + cc) * 4096u,
                             src + (size_t)cc * NS, 4096u, mb);
            }
        }
    }

    // ---- stage feature-path GEMV operands into the free tile region ----
    {
        const float4* W4 = (const float4*)Wfeat;
        float4* Ws = (float4*)(tile + WS_OFF);
        #pragma unroll
        for (int i = tid; i < C_OUT * (C_IN/4); i += 256) Ws[i] = W4[i];
        if (tid < C_OUT) tile[BS_OFF + tid] = bfeat[tid];
    }
    __syncthreads();

    // ---- Phase 2: feature GEMV (two 8-output half-passes) ----
    {
        const float4* Ws = (const float4*)(tile + WS_OFF);
        int nn = n0 + lane;
        #pragma unroll
        for (int half = 0; half < 2; half++) {
            int o0 = warp * 16 + half * 8;
            float acc[8];
            #pragma unroll
            for (int oi = 0; oi < 8; oi++) acc[oi] = tile[BS_OFF + o0 + oi];

            #pragma unroll 4
            for (int c4 = 0; c4 < C_IN/4; c4++) {
                float f0 = aggs[(c4*4+0) * 32 + lane];
                float f1 = aggs[(c4*4+1) * 32 + lane];
                float f2 = aggs[(c4*4+2) * 32 + lane];
                float f3 = aggs[(c4*4+3) * 32 + lane];
                #pragma unroll
                for (int oi = 0; oi < 8; oi++) {
                    float4 w4 = Ws[(o0 + oi) * (C_IN/4) + c4];
                    acc[oi] = fmaf(f0, w4.x, acc[oi]);
                    acc[oi] = fmaf(f1, w4.y, acc[oi]);
                    acc[oi] = fmaf(f2, w4.z, acc[oi]);
                    acc[oi] = fmaf(f3, w4.w, acc[oi]);
                }
            }
            #pragma unroll
            for (int oi = 0; oi < 8; oi++)
                g_ypre[(o0 + oi) * N_PTS + nn] = acc[oi];   // coalesced
        }
    }
    __syncthreads();

    // ---- stage residual operands ----
    {
        const float4* W4 = (const float4*)Wres;
        float4* Ws = (float4*)(tile + WS_OFF);
        #pragma unroll
        for (int i = tid; i < C_OUT * (C_IN/4); i += 256) Ws[i] = W4[i];
        if (tid < C_OUT) tile[BS_OFF + tid] = bres[tid];
    }
    #pragma unroll
    for (int i = tid; i < C_IN * 32; i += 256) {
        int cc = i >> 5, col = i & 31;
        tile[PF_OFF + i] = pf[cc * N_PTS + n0 + col];   // coalesced
    }
    __syncthreads();

    // ---- Phase 3: residual GEMV ----
    {
        const float4* Ws = (const float4*)(tile + WS_OFF);
        int nn = n0 + lane;
        #pragma unroll
        for (int half = 0; half < 2; half++) {
            int o0 = warp * 16 + half * 8;
            float acc[8];
            #pragma unroll
            for (int oi = 0; oi < 8; oi++) acc[oi] = tile[BS_OFF + o0 + oi];

            #pragma unroll 4
            for (int c4 = 0; c4 < C_IN/4; c4++) {
                float f0 = tile[PF_OFF + (c4*4+0) * 32 + lane];
                float f1 = tile[PF_OFF + (c4*4+1) * 32 + lane];
                float f2 = tile[PF_OFF + (c4*4+2) * 32 + lane];
                float f3 = tile[PF_OFF + (c4*4+3) * 32 + lane];
                #pragma unroll
                for (int oi = 0; oi < 8; oi++) {
                    float4 w4 = Ws[(o0 + oi) * (C_IN/4) + c4];
                    acc[oi] = fmaf(f0, w4.x, acc[oi]);
                    acc[oi] = fmaf(f1, w4.y, acc[oi]);
                    acc[oi] = fmaf(f2, w4.z, acc[oi]);
                    acc[oi] = fmaf(f3, w4.w, acc[oi]);
                }
            }
            #pragma unroll
            for (int oi = 0; oi < 8; oi++)
                g_rpre[(o0 + oi) * N_PTS + nn] = acc[oi];
        }
    }
}

// ---------------------------------------------------------------------------
// BN partial stats: 1024 blocks = (path, channel, quarter-row). No atomics.
__global__ __launch_bounds__(256) void k_stats(void)
{
    __shared__ float ws1[8], ws2[8];

    int bid  = blockIdx.x;
    int q    = bid & 3;
    int o    = (bid >> 2) & (C_OUT - 1);
    int path = bid >> 9;
    int tid  = threadIdx.x;

    const float4* src = (const float4*)((path ? g_rpre : g_ypre) + o * N_PTS)
                      + q * (N_PTS / 16);

    float s1 = 0.0f, s2 = 0.0f;
    #pragma unroll
    for (int i = tid; i < N_PTS/16; i += 256) {
        float4 v = src[i];
        s1 += v.x + v.y + v.z + v.w;
        s2 += v.x*v.x + v.y*v.y + v.z*v.z + v.w*v.w;
    }
    #pragma unroll
    for (int off = 16; off; off >>= 1) {
        s1 += __shfl_xor_sync(0xffffffffu, s1, off);
        s2 += __shfl_xor_sync(0xffffffffu, s2, off);
    }
    int warp = tid >> 5, lane = tid & 31;
    if (lane == 0) { ws1[warp] = s1; ws2[warp] = s2; }
    __syncthreads();
    if (tid == 0) {
        float t1 = 0.0f, t2 = 0.0f;
        #pragma unroll
        for (int w = 0; w < 8; w++) { t1 += ws1[w]; t2 += ws2[w]; }
        g_part[bid] = make_float2(t1, t2);
    }
}

// ---------------------------------------------------------------------------
// Finalize: reduce partials + BN coefficients inline, affine + ReLU both
// paths, add, float4 throughout.
__global__ __launch_bounds__(256) void k_final(
    const float* __restrict__ gf, const float* __restrict__ btf,
    const float* __restrict__ gr, const float* __restrict__ btr,
    float* __restrict__ out)
{
    int i4 = blockIdx.x * 256 + threadIdx.x;    // float4 index
    int o  = i4 >> 13;                          // channel
    const float inv = 1.0f / (float)N_PTS;

    float s1f = 0.0f, s2f = 0.0f, s1r = 0.0f, s2r = 0.0f;
    #pragma unroll
    for (int q = 0; q < 4; q++) {
        float2 pF = g_part[(o << 2) + q];
        float2 pR = g_part[(1 << 9) + (o << 2) + q];
        s1f += pF.x; s2f += pF.y;
        s1r += pR.x; s2r += pR.y;
    }

    float mf = s1f * inv;
    float vf = s2f * inv - mf * mf;
    float Af = gf[o] * rsqrtf(vf + EPSBN);
    float Bf = btf[o] - mf * Af;

    float mr = s1r * inv;
    float vr = s2r * inv - mr * mr;
    float Ar = gr[o] * rsqrtf(vr + EPSBN);
    float Br = btr[o] - mr * Ar;

    float4 y = ((const float4*)g_ypre)[i4];
    float4 r = ((const float4*)g_rpre)[i4];
    float4 v;
    v.x = fmaxf(fmaf(y.x, Af, Bf), 0.0f) + fmaxf(fmaf(r.x, Ar, Br), 0.0f);
    v.y = fmaxf(fmaf(y.y, Af, Bf), 0.0f) + fmaxf(fmaf(r.y, Ar, Br), 0.0f);
    v.z = fmaxf(fmaf(y.z, Af, Bf), 0.0f) + fmaxf(fmaf(r.z, Ar, Br), 0.0f);
    v.w = fmaxf(fmaf(y.w, Af, Bf), 0.0f) + fmaxf(fmaf(r.w, Ar, Br), 0.0f);
    ((float4*)out)[i4] = v;
}

// ---------------------------------------------------------------------------
extern "C" void kernel_launch(void* const* d_in, const int* in_sizes, int n_in,
                              void* d_out, int out_size) {
    const float* xyz   = (const float*)d_in[0];
    const float* pf    = (const float*)d_in[1];
    const float* np    = (const float*)d_in[2];
    const float* Wint  = (const float*)d_in[3];
    const float* bint  = (const float*)d_in[4];
    const float* Wfeat = (const float*)d_in[5];
    const float* bfeat = (const float*)d_in[6];
    const float* gfeat = (const float*)d_in[7];
    const float* befeat= (const float*)d_in[8];
    const float* Wres  = (const float*)d_in[9];
    const float* bres  = (const float*)d_in[10];
    const float* gres  = (const float*)d_in[11];
    const float* beres = (const float*)d_in[12];
    float* out = (float*)d_out;

    static bool attr_done = false;
    if (!attr_done) {
        cudaFuncSetAttribute(k_fused, cudaFuncAttributeMaxDynamicSharedMemorySize,
                             SMEM_BYTES);
        attr_done = true;
    }

    k_fused<<<N_PTS / 32, 256, SMEM_BYTES>>>(xyz, np, pf, Wint, bint,
                                             Wfeat, bfeat, Wres, bres);
    k_stats<<<2 * C_OUT * 4, 256>>>();
    k_final<<<(C_OUT * N_PTS / 4) / 256, 256>>>(gfeat, befeat, gres, beres, out);
}

// round 13
// speedup vs baseline: 1.1302x; 1.0023x over previous
#include <cuda_runtime.h>
#include <cstdint>

#define N_PTS   32768
#define S_NBR   32
#define C_IN    64
#define C_OUT   128
#define NS      (N_PTS * S_NBR)   // 1048576
#define EPSBN   1e-5f

// Scratch (device globals; no allocation allowed)
__device__ float  g_ypre[C_OUT * N_PTS];   // [o][n] 16 MB
__device__ float  g_rpre[C_OUT * N_PTS];   // [o][n] 16 MB
__device__ float2 g_part[2 * C_OUT * 4];   // partial (sum,sumsq) per (path,o,quarter)

// ---- dynamic smem layout (float offsets) ----
// tile:  2 bufs x 4 ch x 32 pt x 32 s = 8192 floats (32768 B) [reused as Ws]
// aggs:  64*32                        = 2048 floats ( 8192 B)
// wq:    64 float4                    =  256 floats ( 1024 B)
// bs:    128 floats                   (512 B)
// mbar:  2 x u64
#define AGGS_OFF   8192
#define WQ_OFF     (AGGS_OFF + 2048)          // 10240
#define BS_OFF     (WQ_OFF + 256)             // 10496
#define MBAR_BYTE  ((BS_OFF + 128) * 4)       // 42496
#define SMEM_BYTES (MBAR_BYTE + 32)           // 42528  -> 5 CTAs/SM

// ---------------------------------------------------------------------------
__device__ __forceinline__ uint32_t smem_u32(const void* p) {
    uint32_t a;
    asm("{ .reg .u64 t; cvta.to.shared.u64 t, %1; cvt.u32.u64 %0, t; }"
        : "=r"(a) : "l"(p));
    return a;
}
__device__ __forceinline__ void bulk_g2s(uint32_t dst, const void* src,
                                         uint32_t bytes, uint32_t mbar) {
    asm volatile(
        "cp.async.bulk.shared::cta.global.mbarrier::complete_tx::bytes "
        "[%0], [%1], %2, [%3];"
        :: "r"(dst), "l"(src), "r"(bytes), "r"(mbar) : "memory");
}
__device__ __forceinline__ void mbar_init(uint32_t mbar, uint32_t cnt) {
    asm volatile("mbarrier.init.shared.b64 [%0], %1;" :: "r"(mbar), "r"(cnt) : "memory");
}
__device__ __forceinline__ void mbar_expect_tx(uint32_t mbar, uint32_t bytes) {
    asm volatile("mbarrier.arrive.expect_tx.shared.b64 _, [%0], %1;"
                 :: "r"(mbar), "r"(bytes) : "memory");
}
__device__ __forceinline__ void mbar_wait(uint32_t mbar, uint32_t parity) {
    asm volatile(
        "{\n\t.reg .pred P;\n\t"
        "W_%=:\n\t"
        "mbarrier.try_wait.parity.acquire.cta.shared::cta.b64 P, [%0], %1, 0x989680;\n\t"
        "@!P bra W_%=;\n\t}"
        :: "r"(mbar), "r"(parity) : "memory");
}

// ---------------------------------------------------------------------------
// Fused kernel. Block = 256 threads, 32 points, ~42.5 KB smem -> 5 CTAs/SM.
// Phase 1: 16 chunks of 4 channels via double-buffered cp.async.bulk.
//   Warp owns 4 FIXED points (pt = 4*warp + (lane>>3)); s4 = lane&7.
//   Positions in 12 registers (loaded once, coalesced). Inner loop per
//   channel = 1 LDS.128 + 1 broadcast. 3-shfl reduce over s4 group.
// Phase 2: feature GEMV 64->128 (warp = 16-output slab as 2x8, lane = point),
//   Ws staged into the freed 32 KB tile region.
// Phase 3: residual GEMV; pf read directly from global (coalesced, L1-cached).
__global__ __launch_bounds__(256) void k_fused(
    const float* __restrict__ xyz,     // [N][3]
    const float* __restrict__ np,      // [67][N][S]
    const float* __restrict__ pf,      // [64][N]
    const float* __restrict__ Wint,    // [64][3]
    const float* __restrict__ bint,    // [64]
    const float* __restrict__ Wfeat,   // [128][64]
    const float* __restrict__ bfeat,   // [128]
    const float* __restrict__ Wres,    // [128][64]
    const float* __restrict__ bres)    // [128]
{
    extern __shared__ __align__(16) float smf[];
    float*  tile = smf;                 // 8192 floats (32 KB)
    float*  aggs = smf + AGGS_OFF;      // [c][32]
    float4* wq   = (float4*)(smf + WQ_OFF);
    uint32_t smem_base = smem_u32(smf);
    uint32_t mbar0 = smem_base + MBAR_BYTE;

    int tid  = threadIdx.x;
    int warp = tid >> 5;
    int lane = tid & 31;
    int n0   = blockIdx.x * 32;

    // ---- init barriers, kick off first two chunks (4 ch = 16 KB each) ----
    if (tid == 0) {
        mbar_init(mbar0, 1);
        mbar_init(mbar0 + 8, 1);
        asm volatile("fence.proxy.async.shared::cta;" ::: "memory");
    }
    __syncthreads();
    if (tid == 0) {
        #pragma unroll
        for (int k = 0; k < 2; k++) {
            uint32_t mb = mbar0 + k * 8;
            mbar_expect_tx(mb, 16384u);
            const float* src = np + (size_t)(3 + k * 4) * NS + ((size_t)n0 << 5);
            #pragma unroll
            for (int cc = 0; cc < 4; cc++)
                bulk_g2s(smem_base + (uint32_t)(k * 4 + cc) * 4096u,
                         src + (size_t)cc * NS, 4096u, mb);
        }
    }

    // ---- stage wq (overlaps bulk copies) ----
    if (tid < C_IN)
        wq[tid] = make_float4(Wint[tid*3+0], Wint[tid*3+1], Wint[tid*3+2], bint[tid]);

    // ---- positions: loaded once into registers ----
    int s4  = lane & 7;
    int idx = lane >> 3;
    int pt  = (warp << 2) | idx;        // this thread's point (fixed)
    int n   = n0 + pt;
    float4 px, py, pz;
    {
        unsigned po = ((unsigned)n << 5) + ((unsigned)s4 << 2);
        px = *(const float4*)(np + 0u * NS + po);
        py = *(const float4*)(np + 1u * NS + po);
        pz = *(const float4*)(np + 2u * NS + po);
        float x0 = xyz[n*3+0], x1 = xyz[n*3+1], x2 = xyz[n*3+2];
        px.x -= x0; px.y -= x0; px.z -= x0; px.w -= x0;
        py.x -= x1; py.y -= x1; py.z -= x1; py.w -= x1;
        pz.x -= x2; pz.y -= x2; pz.z -= x2; pz.w -= x2;
    }
    __syncthreads();   // wq visible

    // ---- Phase 1: 16 chunks of 4 channels ----
    {
        const float4* tile4 = (const float4*)tile;
        #pragma unroll 1
        for (int k = 0; k < 16; k++) {
            int b  = k & 1;
            int ph = (k >> 1) & 1;
            mbar_wait(mbar0 + b * 8, (uint32_t)ph);

            #pragma unroll
            for (int ci = 0; ci < 4; ci++) {
                int c = k * 4 + ci;
                float4 w = wq[c];                                      // broadcast
                float4 f = tile4[(b * 4 + ci) * 256 + (pt << 3) + s4]; // 512B/warp

                float h0 = fmaf(w.x, px.x, fmaf(w.y, py.x, fmaf(w.z, pz.x, w.w)));
                float h1 = fmaf(w.x, px.y, fmaf(w.y, py.y, fmaf(w.z, pz.y, w.w)));
                float h2 = fmaf(w.x, px.z, fmaf(w.y, py.z, fmaf(w.z, pz.z, w.w)));
                float h3 = fmaf(w.x, px.w, fmaf(w.y, py.w, fmaf(w.z, pz.w, w.w)));

                float acc;
                acc = fmaxf(h0, 0.0f) * f.x;
                acc = fmaf(fmaxf(h1, 0.0f), f.y, acc);
                acc = fmaf(fmaxf(h2, 0.0f), f.z, acc);
                acc = fmaf(fmaxf(h3, 0.0f), f.w, acc);

                acc += __shfl_xor_sync(0xffffffffu, acc, 1);
                acc += __shfl_xor_sync(0xffffffffu, acc, 2);
                acc += __shfl_xor_sync(0xffffffffu, acc, 4);
                if (s4 == 0) aggs[c * 32 + pt] = acc;   // conflict-free
            }
            __syncthreads();                 // all warps done with buffer b

            if (tid == 0 && k < 14) {        // refill buffer b with chunk k+2
                int kn = k + 2;
                uint32_t mb = mbar0 + b * 8;
                mbar_expect_tx(mb, 16384u);
                const float* src = np + (size_t)(3 + kn * 4) * NS + ((size_t)n0 << 5);
                #pragma unroll
                for (int cc = 0; cc < 4; cc++)
                    bulk_g2s(smem_base + (uint32_t)(b * 4 + cc) * 4096u,
                             src + (size_t)cc * NS, 4096u, mb);
            }
        }
    }

    // ---- stage feature-path GEMV operands into the freed tile (32 KB) ----
    {
        const float4* W4 = (const float4*)Wfeat;
        float4* Ws = (float4*)tile;
        #pragma unroll
        for (int i = tid; i < C_OUT * (C_IN/4); i += 256) Ws[i] = W4[i];
        if (tid < C_OUT) smf[BS_OFF + tid] = bfeat[tid];
    }
    __syncthreads();

    // ---- Phase 2: feature GEMV (two 8-output half-passes) ----
    {
        const float4* Ws = (const float4*)tile;
        int nn = n0 + lane;
        #pragma unroll
        for (int half = 0; half < 2; half++) {
            int o0 = warp * 16 + half * 8;
            float acc[8];
            #pragma unroll
            for (int oi = 0; oi < 8; oi++) acc[oi] = smf[BS_OFF + o0 + oi];

            #pragma unroll 4
            for (int c4 = 0; c4 < C_IN/4; c4++) {
                float f0 = aggs[(c4*4+0) * 32 + lane];
                float f1 = aggs[(c4*4+1) * 32 + lane];
                float f2 = aggs[(c4*4+2) * 32 + lane];
                float f3 = aggs[(c4*4+3) * 32 + lane];
                #pragma unroll
                for (int oi = 0; oi < 8; oi++) {
                    float4 w4 = Ws[(o0 + oi) * (C_IN/4) + c4];
                    acc[oi] = fmaf(f0, w4.x, acc[oi]);
                    acc[oi] = fmaf(f1, w4.y, acc[oi]);
                    acc[oi] = fmaf(f2, w4.z, acc[oi]);
                    acc[oi] = fmaf(f3, w4.w, acc[oi]);
                }
            }
            #pragma unroll
            for (int oi = 0; oi < 8; oi++)
                g_ypre[(o0 + oi) * N_PTS + nn] = acc[oi];   // coalesced
        }
    }
    __syncthreads();

    // ---- stage residual weights ----
    {
        const float4* W4 = (const float4*)Wres;
        float4* Ws = (float4*)tile;
        #pragma unroll
        for (int i = tid; i < C_OUT * (C_IN/4); i += 256) Ws[i] = W4[i];
        if (tid < C_OUT) smf[BS_OFF + tid] = bres[tid];
    }
    __syncthreads();

    // ---- Phase 3: residual GEMV (pf read direct from global, coalesced) ----
    {
        const float4* Ws = (const float4*)tile;
        int nn = n0 + lane;
        #pragma unroll
        for (int half = 0; half < 2; half++) {
            int o0 = warp * 16 + half * 8;
            float acc[8];
            #pragma unroll
            for (int oi = 0; oi < 8; oi++) acc[oi] = smf[BS_OFF + o0 + oi];

            #pragma unroll 4
            for (int c4 = 0; c4 < C_IN/4; c4++) {
                float f0 = pf[(c4*4+0) * N_PTS + nn];
                float f1 = pf[(c4*4+1) * N_PTS + nn];
                float f2 = pf[(c4*4+2) * N_PTS + nn];
                float f3 = pf[(c4*4+3) * N_PTS + nn];
                #pragma unroll
                for (int oi = 0; oi < 8; oi++) {
                    float4 w4 = Ws[(o0 + oi) * (C_IN/4) + c4];
                    acc[oi] = fmaf(f0, w4.x, acc[oi]);
                    acc[oi] = fmaf(f1, w4.y, acc[oi]);
                    acc[oi] = fmaf(f2, w4.z, acc[oi]);
                    acc[oi] = fmaf(f3, w4.w, acc[oi]);
                }
            }
            #pragma unroll
            for (int oi = 0; oi < 8; oi++)
                g_rpre[(o0 + oi) * N_PTS + nn] = acc[oi];
        }
    }
}

// ---------------------------------------------------------------------------
// BN partial stats: 1024 blocks = (path, channel, quarter-row). No atomics.
__global__ __launch_bounds__(256) void k_stats(void)
{
    __shared__ float ws1[8], ws2[8];

    int bid  = blockIdx.x;
    int q    = bid & 3;
    int o    = (bid >> 2) & (C_OUT - 1);
    int path = bid >> 9;
    int tid  = threadIdx.x;

    const float4* src = (const float4*)((path ? g_rpre : g_ypre) + o * N_PTS)
                      + q * (N_PTS / 16);

    float s1 = 0.0f, s2 = 0.0f;
    #pragma unroll
    for (int i = tid; i < N_PTS/16; i += 256) {
        float4 v = src[i];
        s1 += v.x + v.y + v.z + v.w;
        s2 += v.x*v.x + v.y*v.y + v.z*v.z + v.w*v.w;
    }
    #pragma unroll
    for (int off = 16; off; off >>= 1) {
        s1 += __shfl_xor_sync(0xffffffffu, s1, off);
        s2 += __shfl_xor_sync(0xffffffffu, s2, off);
    }
    int warp = tid >> 5, lane = tid & 31;
    if (lane == 0) { ws1[warp] = s1; ws2[warp] = s2; }
    __syncthreads();
    if (tid == 0) {
        float t1 = 0.0f, t2 = 0.0f;
        #pragma unroll
        for (int w = 0; w < 8; w++) { t1 += ws1[w]; t2 += ws2[w]; }
        g_part[bid] = make_float2(t1, t2);
    }
}

// ---------------------------------------------------------------------------
// Finalize: reduce partials + BN coefficients inline, affine + ReLU both
// paths, add, float4 throughout.
__global__ __launch_bounds__(256) void k_final(
    const float* __restrict__ gf, const float* __restrict__ btf,
    const float* __restrict__ gr, const float* __restrict__ btr,
    float* __restrict__ out)
{
    int i4 = blockIdx.x * 256 + threadIdx.x;    // float4 index
    int o  = i4 >> 13;                          // channel
    const float inv = 1.0f / (float)N_PTS;

    float s1f = 0.0f, s2f = 0.0f, s1r = 0.0f, s2r = 0.0f;
    #pragma unroll
    for (int q = 0; q < 4; q++) {
        float2 pF = g_part[(o << 2) + q];
        float2 pR = g_part[(1 << 9) + (o << 2) + q];
        s1f += pF.x; s2f += pF.y;
        s1r += pR.x; s2r += pR.y;
    }

    float mf = s1f * inv;
    float vf = s2f * inv - mf * mf;
    float Af = gf[o] * rsqrtf(vf + EPSBN);
    float Bf = btf[o] - mf * Af;

    float mr = s1r * inv;
    float vr = s2r * inv - mr * mr;
    float Ar = gr[o] * rsqrtf(vr + EPSBN);
    float Br = btr[o] - mr * Ar;

    float4 y = ((const float4*)g_ypre)[i4];
    float4 r = ((const float4*)g_rpre)[i4];
    float4 v;
    v.x = fmaxf(fmaf(y.x, Af, Bf), 0.0f) + fmaxf(fmaf(r.x, Ar, Br), 0.0f);
    v.y = fmaxf(fmaf(y.y, Af, Bf), 0.0f) + fmaxf(fmaf(r.y, Ar, Br), 0.0f);
    v.z = fmaxf(fmaf(y.z, Af, Bf), 0.0f) + fmaxf(fmaf(r.z, Ar, Br), 0.0f);
    v.w = fmaxf(fmaf(y.w, Af, Bf), 0.0f) + fmaxf(fmaf(r.w, Ar, Br), 0.0f);
    ((float4*)out)[i4] = v;
}

// ---------------------------------------------------------------------------
extern "C" void kernel_launch(void* const* d_in, const int* in_sizes, int n_in,
                              void* d_out, int out_size) {
    const float* xyz   = (const float*)d_in[0];
    const float* pf    = (const float*)d_in[1];
    const float* np    = (const float*)d_in[2];
    const float* Wint  = (const float*)d_in[3];
    const float* bint  = (const float*)d_in[4];
    const float* Wfeat = (const float*)d_in[5];
    const float* bfeat = (const float*)d_in[6];
    const float* gfeat = (const float*)d_in[7];
    const float* befeat= (const float*)d_in[8];
    const float* Wres  = (const float*)d_in[9];
    const float* bres  = (const float*)d_in[10];
    const float* gres  = (const float*)d_in[11];
    const float* beres = (const float*)d_in[12];
    float* out = (float*)d_out;

    static bool attr_done = false;
    if (!attr_done) {
        cudaFuncSetAttribute(k_fused, cudaFuncAttributeMaxDynamicSharedMemorySize,
                             SMEM_BYTES);
        attr_done = true;
    }

    k_fused<<<N_PTS / 32, 256, SMEM_BYTES>>>(xyz, np, pf, Wint, bint,
                                             Wfeat, bfeat, Wres, bres);
    k_stats<<<2 * C_OUT * 4, 256>>>();
    k_final<<<(C_OUT * N_PTS / 4) / 256, 256>>>(gfeat, befeat, gres, beres, out);
}

// round 14
// speedup vs baseline: 1.1351x; 1.0043x over previous
#include <cuda_runtime.h>
#include <cstdint>

#define N_PTS   32768
#define S_NBR   32
#define C_IN    64
#define C_OUT   128
#define NS      (N_PTS * S_NBR)   // 1048576
#define EPSBN   1e-5f

// Scratch (device globals; no allocation allowed)
__device__ float  g_ypre[C_OUT * N_PTS];   // [o][n] 16 MB
__device__ float  g_rpre[C_OUT * N_PTS];   // [o][n] 16 MB
__device__ float2 g_part[2 * C_OUT * 4];   // partial (sum,sumsq) per (path,o,quarter)

// ---- dynamic smem layout (float offsets) ----
// tile:  16 slots x 1024 floats = 16384 floats (65536 B)
//        phase 1: 4 pipeline stages x 4 channels x 4KB
//        phase 2/3: Ws (8192 floats) + bs (128) + pf tile (2048)
// aggs:  64*32 = 2048 floats
// wq:    64 float4 = 256 floats
// mbar:  4 x u64
#define AGGS_OFF   16384
#define WQ_OFF     (AGGS_OFF + 2048)          // 18432
#define MBAR_BYTE  ((WQ_OFF + 256) * 4)       // 74752
#define SMEM_BYTES (MBAR_BYTE + 32)           // 74784 -> 3 CTAs/SM

// GEMV staging inside the tile region (float offsets):
#define WS_OFF     0
#define BS_OFF     8192
#define PF_OFF     8320

// ---------------------------------------------------------------------------
__device__ __forceinline__ uint32_t smem_u32(const void* p) {
    uint32_t a;
    asm("{ .reg .u64 t; cvta.to.shared.u64 t, %1; cvt.u32.u64 %0, t; }"
        : "=r"(a) : "l"(p));
    return a;
}
__device__ __forceinline__ void bulk_g2s(uint32_t dst, const void* src,
                                         uint32_t bytes, uint32_t mbar) {
    asm volatile(
        "cp.async.bulk.shared::cta.global.mbarrier::complete_tx::bytes "
        "[%0], [%1], %2, [%3];"
        :: "r"(dst), "l"(src), "r"(bytes), "r"(mbar) : "memory");
}
__device__ __forceinline__ void mbar_init(uint32_t mbar, uint32_t cnt) {
    asm volatile("mbarrier.init.shared.b64 [%0], %1;" :: "r"(mbar), "r"(cnt) : "memory");
}
__device__ __forceinline__ void mbar_expect_tx(uint32_t mbar, uint32_t bytes) {
    asm volatile("mbarrier.arrive.expect_tx.shared.b64 _, [%0], %1;"
                 :: "r"(mbar), "r"(bytes) : "memory");
}
__device__ __forceinline__ void mbar_wait(uint32_t mbar, uint32_t parity) {
    asm volatile(
        "{\n\t.reg .pred P;\n\t"
        "W_%=:\n\t"
        "mbarrier.try_wait.parity.acquire.cta.shared::cta.b64 P, [%0], %1, 0x989680;\n\t"
        "@!P bra W_%=;\n\t}"
        :: "r"(mbar), "r"(parity) : "memory");
}

// ---------------------------------------------------------------------------
// Fused kernel. Block = 256 threads, 32 points, ~74.8 KB smem -> 3 CTAs/SM.
// Phase 1: 16 chunks of 4 channels via a 4-STAGE cp.async.bulk pipeline
//   (64 KB in flight at prologue; refill issued 3 stages before consumption).
//   Warp owns 4 FIXED points (pt = 4*warp + (lane>>3)); s4 = lane&7.
//   Positions in 12 registers. Inner loop per channel = 1 LDS.128 + 1
//   broadcast. 3-shfl reduce over s4 group.
// Phase 2: feature GEMV 64->128 (warp = 16-output slab as 2x8, lane = point),
//   Ws/bias staged into the freed tile region.
// Phase 3: residual GEMV, pf tile staged in smem.
__global__ __launch_bounds__(256) void k_fused(
    const float* __restrict__ xyz,     // [N][3]
    const float* __restrict__ np,      // [67][N][S]
    const float* __restrict__ pf,      // [64][N]
    const float* __restrict__ Wint,    // [64][3]
    const float* __restrict__ bint,    // [64]
    const float* __restrict__ Wfeat,   // [128][64]
    const float* __restrict__ bfeat,   // [128]
    const float* __restrict__ Wres,    // [128][64]
    const float* __restrict__ bres)    // [128]
{
    extern __shared__ __align__(16) float smf[];
    float*  tile = smf;                 // 16384 floats
    float*  aggs = smf + AGGS_OFF;      // [c][32]
    float4* wq   = (float4*)(smf + WQ_OFF);
    uint32_t smem_base = smem_u32(smf);
    uint32_t mbar0 = smem_base + MBAR_BYTE;

    int tid  = threadIdx.x;
    int warp = tid >> 5;
    int lane = tid & 31;
    int n0   = blockIdx.x * 32;

    // ---- init 4 barriers, issue chunks 0..3 (fills whole 64 KB tile) ----
    if (tid == 0) {
        #pragma unroll
        for (int b = 0; b < 4; b++) mbar_init(mbar0 + b * 8, 1);
        asm volatile("fence.proxy.async.shared::cta;" ::: "memory");
    }
    __syncthreads();
    if (tid == 0) {
        #pragma unroll
        for (int k = 0; k < 4; k++) {
            uint32_t mb = mbar0 + k * 8;
            mbar_expect_tx(mb, 16384u);
            const float* src = np + (size_t)(3 + k * 4) * NS + ((size_t)n0 << 5);
            #pragma unroll
            for (int cc = 0; cc < 4; cc++)
                bulk_g2s(smem_base + (uint32_t)(k * 4 + cc) * 4096u,
                         src + (size_t)cc * NS, 4096u, mb);
        }
    }

    // ---- stage wq (overlaps bulk copies) ----
    if (tid < C_IN)
        wq[tid] = make_float4(Wint[tid*3+0], Wint[tid*3+1], Wint[tid*3+2], bint[tid]);

    // ---- positions: loaded once into registers ----
    int s4  = lane & 7;
    int idx = lane >> 3;
    int pt  = (warp << 2) | idx;        // this thread's point (fixed)
    int n   = n0 + pt;
    float4 px, py, pz;
    {
        unsigned po = ((unsigned)n << 5) + ((unsigned)s4 << 2);
        px = *(const float4*)(np + 0u * NS + po);
        py = *(const float4*)(np + 1u * NS + po);
        pz = *(const float4*)(np + 2u * NS + po);
        float x0 = xyz[n*3+0], x1 = xyz[n*3+1], x2 = xyz[n*3+2];
        px.x -= x0; px.y -= x0; px.z -= x0; px.w -= x0;
        py.x -= x1; py.y -= x1; py.z -= x1; py.w -= x1;
        pz.x -= x2; pz.y -= x2; pz.z -= x2; pz.w -= x2;
    }
    __syncthreads();   // wq visible

    // ---- Phase 1: 16 chunks of 4 channels, 4-stage pipeline ----
    {
        const float4* tile4 = (const float4*)tile;
        #pragma unroll 1
        for (int k = 0; k < 16; k++) {
            int b  = k & 3;
            int ph = (k >> 2) & 1;
            mbar_wait(mbar0 + b * 8, (uint32_t)ph);

            #pragma unroll
            for (int ci = 0; ci < 4; ci++) {
                int c = k * 4 + ci;
                float4 w = wq[c];                                      // broadcast
                float4 f = tile4[(b * 4 + ci) * 256 + (pt << 3) + s4]; // 512B/warp

                float h0 = fmaf(w.x, px.x, fmaf(w.y, py.x, fmaf(w.z, pz.x, w.w)));
                float h1 = fmaf(w.x, px.y, fmaf(w.y, py.y, fmaf(w.z, pz.y, w.w)));
                float h2 = fmaf(w.x, px.z, fmaf(w.y, py.z, fmaf(w.z, pz.z, w.w)));
                float h3 = fmaf(w.x, px.w, fmaf(w.y, py.w, fmaf(w.z, pz.w, w.w)));

                float acc;
                acc = fmaxf(h0, 0.0f) * f.x;
                acc = fmaf(fmaxf(h1, 0.0f), f.y, acc);
                acc = fmaf(fmaxf(h2, 0.0f), f.z, acc);
                acc = fmaf(fmaxf(h3, 0.0f), f.w, acc);

                acc += __shfl_xor_sync(0xffffffffu, acc, 1);
                acc += __shfl_xor_sync(0xffffffffu, acc, 2);
                acc += __shfl_xor_sync(0xffffffffu, acc, 4);
                if (s4 == 0) aggs[c * 32 + pt] = acc;   // conflict-free
            }
            __syncthreads();                 // all warps done with buffer b

            if (tid == 0 && k < 12) {        // refill buffer b with chunk k+4
                int kn = k + 4;
                uint32_t mb = mbar0 + b * 8;
                mbar_expect_tx(mb, 16384u);
                const float* src = np + (size_t)(3 + kn * 4) * NS + ((size_t)n0 << 5);
                #pragma unroll
                for (int cc = 0; cc < 4; cc++)
                    bulk_g2s(smem_base + (uint32_t)(b * 4 + cc) * 4096u,
                             src + (size_t)cc * NS, 4096u, mb);
            }
        }
    }

    // ---- stage feature-path GEMV operands into the freed tile region ----
    {
        const float4* W4 = (const float4*)Wfeat;
        float4* Ws = (float4*)(tile + WS_OFF);
        #pragma unroll
        for (int i = tid; i < C_OUT * (C_IN/4); i += 256) Ws[i] = W4[i];
        if (tid < C_OUT) tile[BS_OFF + tid] = bfeat[tid];
    }
    __syncthreads();

    // ---- Phase 2: feature GEMV (two 8-output half-passes) ----
    {
        const float4* Ws = (const float4*)(tile + WS_OFF);
        int nn = n0 + lane;
        #pragma unroll
        for (int half = 0; half < 2; half++) {
            int o0 = warp * 16 + half * 8;
            float acc[8];
            #pragma unroll
            for (int oi = 0; oi < 8; oi++) acc[oi] = tile[BS_OFF + o0 + oi];

            #pragma unroll 4
            for (int c4 = 0; c4 < C_IN/4; c4++) {
                float f0 = aggs[(c4*4+0) * 32 + lane];
                float f1 = aggs[(c4*4+1) * 32 + lane];
                float f2 = aggs[(c4*4+2) * 32 + lane];
                float f3 = aggs[(c4*4+3) * 32 + lane];
                #pragma unroll
                for (int oi = 0; oi < 8; oi++) {
                    float4 w4 = Ws[(o0 + oi) * (C_IN/4) + c4];
                    acc[oi] = fmaf(f0, w4.x, acc[oi]);
                    acc[oi] = fmaf(f1, w4.y, acc[oi]);
                    acc[oi] = fmaf(f2, w4.z, acc[oi]);
                    acc[oi] = fmaf(f3, w4.w, acc[oi]);
                }
            }
            #pragma unroll
            for (int oi = 0; oi < 8; oi++)
                g_ypre[(o0 + oi) * N_PTS + nn] = acc[oi];   // coalesced
        }
    }
    __syncthreads();

    // ---- stage residual operands ----
    {
        const float4* W4 = (const float4*)Wres;
        float4* Ws = (float4*)(tile + WS_OFF);
        #pragma unroll
        for (int i = tid; i < C_OUT * (C_IN/4); i += 256) Ws[i] = W4[i];
        if (tid < C_OUT) tile[BS_OFF + tid] = bres[tid];
    }
    #pragma unroll
    for (int i = tid; i < C_IN * 32; i += 256) {
        int cc = i >> 5, col = i & 31;
        tile[PF_OFF + i] = pf[cc * N_PTS + n0 + col];   // coalesced
    }
    __syncthreads();

    // ---- Phase 3: residual GEMV ----
    {
        const float4* Ws = (const float4*)(tile + WS_OFF);
        int nn = n0 + lane;
        #pragma unroll
        for (int half = 0; half < 2; half++) {
            int o0 = warp * 16 + half * 8;
            float acc[8];
            #pragma unroll
            for (int oi = 0; oi < 8; oi++) acc[oi] = tile[BS_OFF + o0 + oi];

            #pragma unroll 4
            for (int c4 = 0; c4 < C_IN/4; c4++) {
                float f0 = tile[PF_OFF + (c4*4+0) * 32 + lane];
                float f1 = tile[PF_OFF + (c4*4+1) * 32 + lane];
                float f2 = tile[PF_OFF + (c4*4+2) * 32 + lane];
                float f3 = tile[PF_OFF + (c4*4+3) * 32 + lane];
                #pragma unroll
                for (int oi = 0; oi < 8; oi++) {
                    float4 w4 = Ws[(o0 + oi) * (C_IN/4) + c4];
                    acc[oi] = fmaf(f0, w4.x, acc[oi]);
                    acc[oi] = fmaf(f1, w4.y, acc[oi]);
                    acc[oi] = fmaf(f2, w4.z, acc[oi]);
                    acc[oi] = fmaf(f3, w4.w, acc[oi]);
                }
            }
            #pragma unroll
            for (int oi = 0; oi < 8; oi++)
                g_rpre[(o0 + oi) * N_PTS + nn] = acc[oi];
        }
    }
}

// ---------------------------------------------------------------------------
// BN partial stats: 1024 blocks = (path, channel, quarter-row). No atomics.
__global__ __launch_bounds__(256) void k_stats(void)
{
    __shared__ float ws1[8], ws2[8];

    int bid  = blockIdx.x;
    int q    = bid & 3;
    int o    = (bid >> 2) & (C_OUT - 1);
    int path = bid >> 9;
    int tid  = threadIdx.x;

    const float4* src = (const float4*)((path ? g_rpre : g_ypre) + o * N_PTS)
                      + q * (N_PTS / 16);

    float s1 = 0.0f, s2 = 0.0f;
    #pragma unroll
    for (int i = tid; i < N_PTS/16; i += 256) {
        float4 v = src[i];
        s1 += v.x + v.y + v.z + v.w;
        s2 += v.x*v.x + v.y*v.y + v.z*v.z + v.w*v.w;
    }
    #pragma unroll
    for (int off = 16; off; off >>= 1) {
        s1 += __shfl_xor_sync(0xffffffffu, s1, off);
        s2 += __shfl_xor_sync(0xffffffffu, s2, off);
    }
    int warp = tid >> 5, lane = tid & 31;
    if (lane == 0) { ws1[warp] = s1; ws2[warp] = s2; }
    __syncthreads();
    if (tid == 0) {
        float t1 = 0.0f, t2 = 0.0f;
        #pragma unroll
        for (int w = 0; w < 8; w++) { t1 += ws1[w]; t2 += ws2[w]; }
        g_part[bid] = make_float2(t1, t2);
    }
}

// ---------------------------------------------------------------------------
// Finalize: reduce partials + BN coefficients inline, affine + ReLU both
// paths, add, float4 throughout.
__global__ __launch_bounds__(256) void k_final(
    const float* __restrict__ gf, const float* __restrict__ btf,
    const float* __restrict__ gr, const float* __restrict__ btr,
    float* __restrict__ out)
{
    int i4 = blockIdx.x * 256 + threadIdx.x;    // float4 index
    int o  = i4 >> 13;                          // channel
    const float inv = 1.0f / (float)N_PTS;

    float s1f = 0.0f, s2f = 0.0f, s1r = 0.0f, s2r = 0.0f;
    #pragma unroll
    for (int q = 0; q < 4; q++) {
        float2 pF = g_part[(o << 2) + q];
        float2 pR = g_part[(1 << 9) + (o << 2) + q];
        s1f += pF.x; s2f += pF.y;
        s1r += pR.x; s2r += pR.y;
    }

    float mf = s1f * inv;
    float vf = s2f * inv - mf * mf;
    float Af = gf[o] * rsqrtf(vf + EPSBN);
    float Bf = btf[o] - mf * Af;

    float mr = s1r * inv;
    float vr = s2r * inv - mr * mr;
    float Ar = gr[o] * rsqrtf(vr + EPSBN);
    float Br = btr[o] - mr * Ar;

    float4 y = ((const float4*)g_ypre)[i4];
    float4 r = ((const float4*)g_rpre)[i4];
    float4 v;
    v.x = fmaxf(fmaf(y.x, Af, Bf), 0.0f) + fmaxf(fmaf(r.x, Ar, Br), 0.0f);
    v.y = fmaxf(fmaf(y.y, Af, Bf), 0.0f) + fmaxf(fmaf(r.y, Ar, Br), 0.0f);
    v.z = fmaxf(fmaf(y.z, Af, Bf), 0.0f) + fmaxf(fmaf(r.z, Ar, Br), 0.0f);
    v.w = fmaxf(fmaf(y.w, Af, Bf), 0.0f) + fmaxf(fmaf(r.w, Ar, Br), 0.0f);
    ((float4*)out)[i4] = v;
}

// ---------------------------------------------------------------------------
extern "C" void kernel_launch(void* const* d_in, const int* in_sizes, int n_in,
                              void* d_out, int out_size) {
    const float* xyz   = (const float*)d_in[0];
    const float* pf    = (const float*)d_in[1];
    const float* np    = (const float*)d_in[2];
    const float* Wint  = (const float*)d_in[3];
    const float* bint  = (const float*)d_in[4];
    const float* Wfeat = (const float*)d_in[5];
    const float* bfeat = (const float*)d_in[6];
    const float* gfeat = (const float*)d_in[7];
    const float* befeat= (const float*)d_in[8];
    const float* Wres  = (const float*)d_in[9];
    const float* bres  = (const float*)d_in[10];
    const float* gres  = (const float*)d_in[11];
    const float* beres = (const float*)d_in[12];
    float* out = (float*)d_out;

    static bool attr_done = false;
    if (!attr_done) {
        cudaFuncSetAttribute(k_fused, cudaFuncAttributeMaxDynamicSharedMemorySize,
                             SMEM_BYTES);
        attr_done = true;
    }

    k_fused<<<N_PTS / 32, 256, SMEM_BYTES>>>(xyz, np, pf, Wint, bint,
                                             Wfeat, bfeat, Wres, bres);
    k_stats<<<2 * C_OUT * 4, 256>>>();
    k_final<<<(C_OUT * N_PTS / 4) / 256, 256>>>(gfeat, befeat, gres, beres, out);
}